// round 6
// baseline (speedup 1.0000x reference)
#include <cuda_runtime.h>
#include <cuda_fp16.h>

#define B_ROWS   16384
#define K_FEATS  32
#define H_DIM    256
#define FULLMASK 0xFFFFFFFFu

#define TILE      16        // rows per block
#define XS_STRIDE 516       // floats per staged row (512 + 4 pad, conflict-free)

#define TBL_BLOCKS 5120     // blocks of prep_all doing the fp16 table

// fp16 copy of ft_w: 40960 x 256 halves = 20MB (128 half2 per row)
__device__ __half2 g_ftw_h[40960 * 128];
// fc1_w transposed: [iq][j] float4 (iq over 512/4 inputs, j = 0..31 outputs)
__device__ float4 g_fc1T[128 * 32];

// ---- merged prep: fp16 table (blocks < TBL_BLOCKS) + fc1 transpose (rest) ----
__global__ __launch_bounds__(256) void prep_all(const float* __restrict__ ft_w,
                                                const float* __restrict__ fc1_w) {
    const int b = blockIdx.x;
    if (b < TBL_BLOCKS) {
        int i = b * blockDim.x + threadIdx.x;   // over 1,310,720 8-float chunks
        const float4 v0 = __ldcs((const float4*)ft_w + i * 2);
        const float4 v1 = __ldcs((const float4*)ft_w + i * 2 + 1);
        uint4 r;
        __half2 h0 = __floats2half2_rn(v0.x, v0.y);
        __half2 h1 = __floats2half2_rn(v0.z, v0.w);
        __half2 h2 = __floats2half2_rn(v1.x, v1.y);
        __half2 h3 = __floats2half2_rn(v1.z, v1.w);
        r.x = *(unsigned*)&h0; r.y = *(unsigned*)&h1;
        r.z = *(unsigned*)&h2; r.w = *(unsigned*)&h3;
        ((uint4*)g_ftw_h)[i] = r;
    } else {
        int t = (b - TBL_BLOCKS) * blockDim.x + threadIdx.x;
        if (t < 128 * 32) {
            int iq = t >> 5;
            int j  = t & 31;
            const float* p = fc1_w + j * 512 + iq * 4;
            g_fc1T[t] = make_float4(p[0], p[1], p[2], p[3]);
        }
    }
}

__device__ __forceinline__ float4 clip01(float4 v) {
    v.x = fminf(fmaxf(v.x, 0.0f), 1.0f);
    v.y = fminf(fmaxf(v.y, 0.0f), 1.0f);
    v.z = fminf(fmaxf(v.z, 0.0f), 1.0f);
    v.w = fminf(fmaxf(v.w, 0.0f), 1.0f);
    return v;
}

// ---- packed f32x2 helpers (Blackwell FFMA2) ----
__device__ __forceinline__ unsigned long long pack_f32x2(float lo, float hi) {
    unsigned long long r;
    asm("mov.b64 %0, {%1, %2};" : "=l"(r) : "f"(lo), "f"(hi));
    return r;
}
__device__ __forceinline__ void unpack_f32x2(unsigned long long v, float& lo, float& hi) {
    asm("mov.b64 {%0, %1}, %2;" : "=f"(lo), "=f"(hi) : "l"(v));
}
// acc += h2f(w_h2) * m2   (packed fp32 pair, exact fp32 math)
__device__ __forceinline__ void ffma2_h2(unsigned long long& acc, unsigned wbits,
                                         unsigned long long m2) {
    asm("{\n\t"
        ".reg .f32 lo, hi;\n\t"
        ".reg .b16 l16, h16;\n\t"
        ".reg .b64 ab;\n\t"
        "mov.b32 {l16, h16}, %1;\n\t"
        "cvt.f32.f16 lo, l16;\n\t"
        "cvt.f32.f16 hi, h16;\n\t"
        "mov.b64 ab, {lo, hi};\n\t"
        "fma.rn.f32x2 %0, ab, %2, %0;\n\t"
        "}"
        : "+l"(acc) : "r"(wbits), "l"(m2));
}
// accumulate 8 fp16 values (one uint4) scaled by packed m2 into 4 f32x2 accumulators
__device__ __forceinline__ void acc8p(unsigned long long* a, unsigned long long m2, uint4 r) {
    ffma2_h2(a[0], r.x, m2);
    ffma2_h2(a[1], r.y, m2);
    ffma2_h2(a[2], r.z, m2);
    ffma2_h2(a[3], r.w, m2);
}

__global__ __launch_bounds__(256, 4)
void nnue_kernel(const int*   __restrict__ wft_ics,
                 const float* __restrict__ wft_vals,
                 const int*   __restrict__ bft_ics,
                 const float* __restrict__ bft_vals,
                 const int*   __restrict__ stm,
                 const float* __restrict__ ft_b,
                 const float* __restrict__ fc1_b,
                 const float* __restrict__ fc2_w,
                 const float* __restrict__ fc2_b,
                 const float* __restrict__ fco_w,
                 const float* __restrict__ fco_b,
                 float*       __restrict__ out)
{
    // s_feat[r][k] = (w_off_half2, w_val_bits, b_off_half2, b_val_bits); padded -> val_bits=0
    __shared__ int4  s_feat[TILE][K_FEATS];     // 8 KB
    __shared__ float xs[TILE * XS_STRIDE];      // staged x[512]/row fp32, padded  33 KB
    __shared__ float fc2T[32 * 32];             // fc2T[i*32+j] = fc2_w[j][i]      4 KB
    __shared__ float h1s[TILE * 33];            // clipped FC1 activations         2.1 KB
    __shared__ int   s_stm[TILE];

    const int tid  = threadIdx.x;
    const int lane = tid & 31;
    const int warp = tid >> 5;               // 0..7
    const int row0 = blockIdx.x * TILE;

    // ---- staging ----
    for (int idx = tid; idx < 1024; idx += 256)
        fc2T[(idx & 31) * 32 + (idx >> 5)] = fc2_w[idx];
    if (tid < TILE)
        s_stm[tid] = stm[row0 + tid];

    #pragma unroll
    for (int e = tid; e < TILE * K_FEATS; e += 256) {
        const int r  = e >> 5;
        const int k  = e & 31;
        const int gi = (row0 + r) * K_FEATS + k;
        const int   wi = __ldg(wft_ics + gi);
        const float wv = __ldg(wft_vals + gi);
        const int   bi = __ldg(bft_ics + gi);
        const float bv = __ldg(bft_vals + gi);
        s_feat[r][k] = make_int4(wi >= 0 ? wi * 128 : 0,
                                 __float_as_int(wi >= 0 ? wv : 0.0f),
                                 bi >= 0 ? bi * 128 : 0,
                                 __float_as_int(bi >= 0 ? bv : 0.0f));
    }

    // per-lane ft bias (cols lane*8 .. lane*8+7) packed into f32x2 pairs
    unsigned long long bias[4];
    {
        const float4 b0 = *(const float4*)(ft_b + lane * 8);
        const float4 b1 = *(const float4*)(ft_b + lane * 8 + 4);
        bias[0] = pack_f32x2(b0.x, b0.y);
        bias[1] = pack_f32x2(b0.z, b0.w);
        bias[2] = pack_f32x2(b1.x, b1.y);
        bias[3] = pack_f32x2(b1.z, b1.w);
    }

    __syncthreads();

    // ---------------- Phase 1: gather (warp w -> rows 2w, 2w+1) ----------------
    #pragma unroll
    for (int rr = 0; rr < 2; rr++) {
        const int r = warp * 2 + rr;

        unsigned long long aw[4] = { bias[0], bias[1], bias[2], bias[3] };
        unsigned long long ab[4] = { bias[0], bias[1], bias[2], bias[3] };

        #pragma unroll 4
        for (int k = 0; k < K_FEATS; k++) {
            const int4 f = s_feat[r][k];     // broadcast LDS.128 (warp-uniform)
            // uniform skip of padded slots (val bits == 0): no divergence
            if (f.y != 0) {
                const uint4 rw = __ldcg((const uint4*)(g_ftw_h + f.x) + lane);
                const float m = __int_as_float(f.y);
                acc8p(aw, pack_f32x2(m, m), rw);
            }
            if (f.w != 0) {
                const uint4 rb = __ldcg((const uint4*)(g_ftw_h + f.z) + lane);
                const float m = __int_as_float(f.w);
                acc8p(ab, pack_f32x2(m, m), rb);
            }
        }

        // unpack accumulators
        float4 aw0, aw1, ab0, ab1;
        unpack_f32x2(aw[0], aw0.x, aw0.y);  unpack_f32x2(aw[1], aw0.z, aw0.w);
        unpack_f32x2(aw[2], aw1.x, aw1.y);  unpack_f32x2(aw[3], aw1.z, aw1.w);
        unpack_f32x2(ab[0], ab0.x, ab0.y);  unpack_f32x2(ab[1], ab0.z, ab0.w);
        unpack_f32x2(ab[2], ab1.x, ab1.y);  unpack_f32x2(ab[3], ab1.z, ab1.w);

        // stm-conditional swap + clip, store fp32 x
        const int s = s_stm[r];
        float4 lo0, lo1, hi0, hi1;
        if (s) { lo0 = ab0; lo1 = ab1; hi0 = aw0; hi1 = aw1; }
        else   { lo0 = aw0; lo1 = aw1; hi0 = ab0; hi1 = ab1; }

        float4* xr = (float4*)(xs + r * XS_STRIDE);
        xr[lane * 2]          = clip01(lo0);
        xr[lane * 2 + 1]      = clip01(lo1);
        xr[64 + lane * 2]     = clip01(hi0);
        xr[64 + lane * 2 + 1] = clip01(hi1);
    }

    __syncthreads();

    // ---------------- Phase 2: FC1 (lane j = output j; warp w -> rows 2w, 2w+1) ------
    const int j = lane;
    const float b1j = __ldg(fc1_b + j);
    float h1a = b1j, h1b = b1j;

    const int r0 = warp * 2;
    const float4* x0 = (const float4*)(xs + r0 * XS_STRIDE);
    const float4* x1 = (const float4*)(xs + (r0 + 1) * XS_STRIDE);

    #pragma unroll 4
    for (int iq = 0; iq < 128; iq++) {
        const float4 w  = g_fc1T[iq * 32 + j];  // coalesced 512B, L1-hot
        const float4 xa = x0[iq];               // broadcast LDS.128
        const float4 xb = x1[iq];
        h1a = fmaf(w.x, xa.x, fmaf(w.y, xa.y, fmaf(w.z, xa.z, fmaf(w.w, xa.w, h1a))));
        h1b = fmaf(w.x, xb.x, fmaf(w.y, xb.y, fmaf(w.z, xb.z, fmaf(w.w, xb.w, h1b))));
    }

    h1s[r0 * 33 + j]       = fminf(fmaxf(h1a, 0.0f), 1.0f);
    h1s[(r0 + 1) * 33 + j] = fminf(fmaxf(h1b, 0.0f), 1.0f);

    __syncthreads();

    // ---------------- FC2 + output head: warp w -> rows 2w, 2w+1 ----------------------
    const float b2j = __ldg(fc2_b + lane);
    const float fcw = __ldg(fco_w + lane);
    const float fcb = __ldg(fco_b);

    #pragma unroll
    for (int rr = 0; rr < 2; rr++) {
        const int row = warp * 2 + rr;
        float h2 = b2j;
        #pragma unroll
        for (int i = 0; i < 32; i++)
            h2 = fmaf(fc2T[i * 32 + lane], h1s[row * 33 + i], h2);
        h2 = fminf(fmaxf(h2, 0.0f), 1.0f);

        float o = h2 * fcw;
        #pragma unroll
        for (int off = 16; off; off >>= 1)
            o += __shfl_xor_sync(FULLMASK, o, off);

        if (lane == 0)
            out[row0 + row] = o + fcb;
    }
}

extern "C" void kernel_launch(void* const* d_in, const int* in_sizes, int n_in,
                              void* d_out, int out_size)
{
    const int*   wft_ics  = (const int*)  d_in[0];
    const float* wft_vals = (const float*)d_in[1];
    const int*   bft_ics  = (const int*)  d_in[2];
    const float* bft_vals = (const float*)d_in[3];
    const int*   stm      = (const int*)  d_in[4];
    const float* ft_w     = (const float*)d_in[5];
    const float* ft_b     = (const float*)d_in[6];
    const float* fc1_w    = (const float*)d_in[7];
    const float* fc1_b    = (const float*)d_in[8];
    const float* fc2_w    = (const float*)d_in[9];
    const float* fc2_b    = (const float*)d_in[10];
    const float* fco_w    = (const float*)d_in[11];
    const float* fco_b    = (const float*)d_in[12];
    float* out = (float*)d_out;

    // table: 5120 blocks; fc1 transpose: 16 more blocks
    prep_all<<<TBL_BLOCKS + 16, 256>>>(ft_w, fc1_w);
    nnue_kernel<<<B_ROWS / TILE, 256>>>(wft_ics, wft_vals, bft_ics, bft_vals, stm,
                                        ft_b, fc1_b, fc2_w, fc2_b,
                                        fco_w, fco_b, out);
}

// round 7
// speedup vs baseline: 1.0024x; 1.0024x over previous
#include <cuda_runtime.h>
#include <cuda_fp16.h>

#define B_ROWS   16384
#define K_FEATS  32
#define H_DIM    256
#define FULLMASK 0xFFFFFFFFu

#define TILE      16        // rows per block
#define XS_STRIDE 516       // floats per staged row (512 + 4 pad, conflict-free)

#define TBL_BLOCKS 5120     // blocks of prep_all doing the fp16 table

// fp16 copy of ft_w: 40960 x 256 halves = 20MB (128 half2 per row)
__device__ __half2 g_ftw_h[40960 * 128];
// fc1_w transposed: [iq][j] float4 (iq over 512/4 inputs, j = 0..31 outputs)
__device__ float4 g_fc1T[128 * 32];

// ---- merged prep: fp16 table (blocks < TBL_BLOCKS) + fc1 transpose (rest) ----
__global__ __launch_bounds__(256) void prep_all(const float* __restrict__ ft_w,
                                                const float* __restrict__ fc1_w) {
    const int b = blockIdx.x;
    if (b < TBL_BLOCKS) {
        int i = b * blockDim.x + threadIdx.x;   // over 1,310,720 8-float chunks
        const float4 v0 = __ldcs((const float4*)ft_w + i * 2);
        const float4 v1 = __ldcs((const float4*)ft_w + i * 2 + 1);
        uint4 r;
        __half2 h0 = __floats2half2_rn(v0.x, v0.y);
        __half2 h1 = __floats2half2_rn(v0.z, v0.w);
        __half2 h2 = __floats2half2_rn(v1.x, v1.y);
        __half2 h3 = __floats2half2_rn(v1.z, v1.w);
        r.x = *(unsigned*)&h0; r.y = *(unsigned*)&h1;
        r.z = *(unsigned*)&h2; r.w = *(unsigned*)&h3;
        ((uint4*)g_ftw_h)[i] = r;
    } else {
        int t = (b - TBL_BLOCKS) * blockDim.x + threadIdx.x;
        if (t < 128 * 32) {
            int iq = t >> 5;
            int j  = t & 31;
            const float* p = fc1_w + j * 512 + iq * 4;
            g_fc1T[t] = make_float4(p[0], p[1], p[2], p[3]);
        }
    }
}

__device__ __forceinline__ float4 clip01(float4 v) {
    v.x = fminf(fmaxf(v.x, 0.0f), 1.0f);
    v.y = fminf(fmaxf(v.y, 0.0f), 1.0f);
    v.z = fminf(fmaxf(v.z, 0.0f), 1.0f);
    v.w = fminf(fmaxf(v.w, 0.0f), 1.0f);
    return v;
}

// ---- packed f32x2 helpers (Blackwell FFMA2) ----
__device__ __forceinline__ unsigned long long pack_f32x2(float lo, float hi) {
    unsigned long long r;
    asm("mov.b64 %0, {%1, %2};" : "=l"(r) : "f"(lo), "f"(hi));
    return r;
}
__device__ __forceinline__ void unpack_f32x2(unsigned long long v, float& lo, float& hi) {
    asm("mov.b64 {%0, %1}, %2;" : "=f"(lo), "=f"(hi) : "l"(v));
}
// acc += h2f(w_h2) * m2   (packed fp32 pair, exact fp32 math)
__device__ __forceinline__ void ffma2_h2(unsigned long long& acc, unsigned wbits,
                                         unsigned long long m2) {
    asm("{\n\t"
        ".reg .f32 lo, hi;\n\t"
        ".reg .b16 l16, h16;\n\t"
        ".reg .b64 ab;\n\t"
        "mov.b32 {l16, h16}, %1;\n\t"
        "cvt.f32.f16 lo, l16;\n\t"
        "cvt.f32.f16 hi, h16;\n\t"
        "mov.b64 ab, {lo, hi};\n\t"
        "fma.rn.f32x2 %0, ab, %2, %0;\n\t"
        "}"
        : "+l"(acc) : "r"(wbits), "l"(m2));
}
// accumulate 8 fp16 values (one uint4) scaled by packed m2 into 4 f32x2 accumulators
__device__ __forceinline__ void acc8p(unsigned long long* a, unsigned long long m2, uint4 r) {
    ffma2_h2(a[0], r.x, m2);
    ffma2_h2(a[1], r.y, m2);
    ffma2_h2(a[2], r.z, m2);
    ffma2_h2(a[3], r.w, m2);
}

__global__ __launch_bounds__(256, 4)
void nnue_kernel(const int*   __restrict__ wft_ics,
                 const float* __restrict__ wft_vals,
                 const int*   __restrict__ bft_ics,
                 const float* __restrict__ bft_vals,
                 const int*   __restrict__ stm,
                 const float* __restrict__ ft_b,
                 const float* __restrict__ fc1_b,
                 const float* __restrict__ fc2_w,
                 const float* __restrict__ fc2_b,
                 const float* __restrict__ fco_w,
                 const float* __restrict__ fco_b,
                 float*       __restrict__ out)
{
    // s_feat[r][k] = (w_off_half2, w_val_bits, b_off_half2, b_val_bits); padded -> val_bits=0
    __shared__ int4  s_feat[TILE][K_FEATS];     // 8 KB
    __shared__ float xs[TILE * XS_STRIDE];      // staged x[512]/row fp32, padded  33 KB
    __shared__ float fc2T[32 * 32];             // fc2T[i*32+j] = fc2_w[j][i]      4 KB
    __shared__ float h1s[TILE * 33];            // clipped FC1 activations         2.1 KB
    __shared__ int   s_stm[TILE];

    const int tid  = threadIdx.x;
    const int lane = tid & 31;
    const int warp = tid >> 5;               // 0..7
    const int row0 = blockIdx.x * TILE;

    // ---- staging ----
    for (int idx = tid; idx < 1024; idx += 256)
        fc2T[(idx & 31) * 32 + (idx >> 5)] = fc2_w[idx];
    if (tid < TILE)
        s_stm[tid] = stm[row0 + tid];

    #pragma unroll
    for (int e = tid; e < TILE * K_FEATS; e += 256) {
        const int r  = e >> 5;
        const int k  = e & 31;
        const int gi = (row0 + r) * K_FEATS + k;
        const int   wi = __ldg(wft_ics + gi);
        const float wv = __ldg(wft_vals + gi);
        const int   bi = __ldg(bft_ics + gi);
        const float bv = __ldg(bft_vals + gi);
        s_feat[r][k] = make_int4(wi >= 0 ? wi * 128 : 0,
                                 __float_as_int(wi >= 0 ? wv : 0.0f),
                                 bi >= 0 ? bi * 128 : 0,
                                 __float_as_int(bi >= 0 ? bv : 0.0f));
    }

    // per-lane ft bias (cols lane*8 .. lane*8+7) packed into f32x2 pairs
    unsigned long long bias[4];
    {
        const float4 b0 = *(const float4*)(ft_b + lane * 8);
        const float4 b1 = *(const float4*)(ft_b + lane * 8 + 4);
        bias[0] = pack_f32x2(b0.x, b0.y);
        bias[1] = pack_f32x2(b0.z, b0.w);
        bias[2] = pack_f32x2(b1.x, b1.y);
        bias[3] = pack_f32x2(b1.z, b1.w);
    }

    __syncthreads();

    // ---------------- Phase 1: gather (warp w -> rows 2w, 2w+1) ----------------
    #pragma unroll
    for (int rr = 0; rr < 2; rr++) {
        const int r = warp * 2 + rr;

        unsigned long long aw[4] = { bias[0], bias[1], bias[2], bias[3] };
        unsigned long long ab[4] = { bias[0], bias[1], bias[2], bias[3] };

        #pragma unroll 4
        for (int k = 0; k < K_FEATS; k++) {
            const int4 f = s_feat[r][k];     // broadcast LDS.128 (warp-uniform)
            // uniform skip of padded slots (val bits == 0): no divergence
            if (f.y != 0) {
                const uint4 rw = __ldcg((const uint4*)(g_ftw_h + f.x) + lane);
                const float m = __int_as_float(f.y);
                acc8p(aw, pack_f32x2(m, m), rw);
            }
            if (f.w != 0) {
                const uint4 rb = __ldcg((const uint4*)(g_ftw_h + f.z) + lane);
                const float m = __int_as_float(f.w);
                acc8p(ab, pack_f32x2(m, m), rb);
            }
        }

        // unpack accumulators
        float4 aw0, aw1, ab0, ab1;
        unpack_f32x2(aw[0], aw0.x, aw0.y);  unpack_f32x2(aw[1], aw0.z, aw0.w);
        unpack_f32x2(aw[2], aw1.x, aw1.y);  unpack_f32x2(aw[3], aw1.z, aw1.w);
        unpack_f32x2(ab[0], ab0.x, ab0.y);  unpack_f32x2(ab[1], ab0.z, ab0.w);
        unpack_f32x2(ab[2], ab1.x, ab1.y);  unpack_f32x2(ab[3], ab1.z, ab1.w);

        // stm-conditional swap + clip, store fp32 x
        const int s = s_stm[r];
        float4 lo0, lo1, hi0, hi1;
        if (s) { lo0 = ab0; lo1 = ab1; hi0 = aw0; hi1 = aw1; }
        else   { lo0 = aw0; lo1 = aw1; hi0 = ab0; hi1 = ab1; }

        float4* xr = (float4*)(xs + r * XS_STRIDE);
        xr[lane * 2]          = clip01(lo0);
        xr[lane * 2 + 1]      = clip01(lo1);
        xr[64 + lane * 2]     = clip01(hi0);
        xr[64 + lane * 2 + 1] = clip01(hi1);
    }

    __syncthreads();

    // ---------------- Phase 2: FC1, mapping B --------------------------------------
    // warp = half*4 + g : rows half*8 .. half*8+7, outputs j = g*8 .. g*8+7
    // lane = rg*8 + jo  : this thread handles rows (half*8 + rg*2, +1), output g*8+jo
    // Weight load per iq: 8 distinct consecutive float4 = one 128B line, 4-way bcast.
    // xs loads per iq: 4 distinct rows, bank offsets {0,8,16,24} -> conflict-free.
    {
        const int jo   = lane & 7;
        const int rg   = lane >> 3;
        const int g    = warp & 3;
        const int half = warp >> 2;
        const int j    = g * 8 + jo;
        const int r0   = half * 8 + rg * 2;

        const float b1j = __ldg(fc1_b + j);
        float h1a = b1j, h1b = b1j;

        const float4* x0 = (const float4*)(xs + r0 * XS_STRIDE);
        const float4* x1 = (const float4*)(xs + (r0 + 1) * XS_STRIDE);

        #pragma unroll 4
        for (int iq = 0; iq < 128; iq++) {
            const float4 w  = g_fc1T[iq * 32 + j];  // 128B line per warp, L1-hot
            const float4 xa = x0[iq];
            const float4 xb = x1[iq];
            h1a = fmaf(w.x, xa.x, fmaf(w.y, xa.y, fmaf(w.z, xa.z, fmaf(w.w, xa.w, h1a))));
            h1b = fmaf(w.x, xb.x, fmaf(w.y, xb.y, fmaf(w.z, xb.z, fmaf(w.w, xb.w, h1b))));
        }

        h1s[r0 * 33 + j]       = fminf(fmaxf(h1a, 0.0f), 1.0f);
        h1s[(r0 + 1) * 33 + j] = fminf(fmaxf(h1b, 0.0f), 1.0f);
    }

    __syncthreads();

    // ---------------- FC2 + output head: warp w -> rows 2w, 2w+1 ----------------------
    const float b2j = __ldg(fc2_b + lane);
    const float fcw = __ldg(fco_w + lane);
    const float fcb = __ldg(fco_b);

    #pragma unroll
    for (int rr = 0; rr < 2; rr++) {
        const int row = warp * 2 + rr;
        float h2 = b2j;
        #pragma unroll
        for (int i = 0; i < 32; i++)
            h2 = fmaf(fc2T[i * 32 + lane], h1s[row * 33 + i], h2);
        h2 = fminf(fmaxf(h2, 0.0f), 1.0f);

        float o = h2 * fcw;
        #pragma unroll
        for (int off = 16; off; off >>= 1)
            o += __shfl_xor_sync(FULLMASK, o, off);

        if (lane == 0)
            out[row0 + row] = o + fcb;
    }
}

extern "C" void kernel_launch(void* const* d_in, const int* in_sizes, int n_in,
                              void* d_out, int out_size)
{
    const int*   wft_ics  = (const int*)  d_in[0];
    const float* wft_vals = (const float*)d_in[1];
    const int*   bft_ics  = (const int*)  d_in[2];
    const float* bft_vals = (const float*)d_in[3];
    const int*   stm      = (const int*)  d_in[4];
    const float* ft_w     = (const float*)d_in[5];
    const float* ft_b     = (const float*)d_in[6];
    const float* fc1_w    = (const float*)d_in[7];
    const float* fc1_b    = (const float*)d_in[8];
    const float* fc2_w    = (const float*)d_in[9];
    const float* fc2_b    = (const float*)d_in[10];
    const float* fco_w    = (const float*)d_in[11];
    const float* fco_b    = (const float*)d_in[12];
    float* out = (float*)d_out;

    // table: 5120 blocks; fc1 transpose: 16 more blocks
    prep_all<<<TBL_BLOCKS + 16, 256>>>(ft_w, fc1_w);
    nnue_kernel<<<B_ROWS / TILE, 256>>>(wft_ics, wft_vals, bft_ics, bft_vals, stm,
                                        ft_b, fc1_b, fc2_w, fc2_b,
                                        fco_w, fco_b, out);
}